// round 6
// baseline (speedup 1.0000x reference)
#include <cuda_runtime.h>
#include <cstdint>

// DIN attention-seq-pooling, round 6: mma.sync tf32, no k smem.
// vs round 5: A-fragments (k) load straight from global (warp-exclusive rows,
// no reuse), pooling reads k from global coalesced. smem 115.5KB -> 58.9KB
// => 3 CTAs/SM (was 2). CTA = one batch, 4 warps, warp owns 16-token tiles.
//  MMA1: D1[16,80] = k[16,64] @ B1eff[64,80]  (B1eff per-batch, tf32)
//  h1 = sigmoid(D1 + qW) -> per-warp smem buffer (tf32 bits, stride 84)
//  MMA2: D2[16,40] = h1[16,80] @ W2T[80,40]
//  score = sigmoid(D2+b2)@Wd + bd, mask t<L; pool out = sum score_t * k_t.

#define TT 200
#define EE 64
#define HH1 80
#define HH2 40
#define B1STRIDE 68    // ≡4 mod 32 -> conflict-free B fragment loads
#define H1STRIDE 84    // >=80, ≡20 mod 32 -> conflict-free
#define W2TSTRIDE 84

typedef unsigned long long ull;

__device__ float  g_W1sum[EE * HH1];        // W1a + W1c
__device__ float2 g_W1pair[EE * HH1];       // {W1b - W1c, W1d}, layout [e][n]
__device__ float  g_qW[4096 * HH1];         // b1 + q @ W1sum
__device__ unsigned g_W2T[HH2 * W2TSTRIDE]; // tf32 image, [n][k] k<80 else 0

__device__ __forceinline__ unsigned cvt_tf32(float x) {
    unsigned r; asm("cvt.rna.tf32.f32 %0, %1;" : "=r"(r) : "f"(x)); return r;
}
__device__ __forceinline__ float sigmoidf_fast(float x) {
    return __fdividef(1.0f, 1.0f + __expf(-x));
}
__device__ __forceinline__ void mma_tf32(float* d, unsigned a0, unsigned a1,
                                         unsigned a2, unsigned a3,
                                         unsigned b0, unsigned b1) {
    asm volatile(
        "mma.sync.aligned.m16n8k8.row.col.f32.tf32.tf32.f32 "
        "{%0,%1,%2,%3}, {%4,%5,%6,%7}, {%8,%9}, {%0,%1,%2,%3};"
        : "+f"(d[0]), "+f"(d[1]), "+f"(d[2]), "+f"(d[3])
        : "r"(a0), "r"(a1), "r"(a2), "r"(a3), "r"(b0), "r"(b1));
}

// ---------------- prep kernels ----------------
__global__ void prep_pack(const float* __restrict__ W1, const float* __restrict__ W2) {
    int i = blockIdx.x * 256 + threadIdx.x;
    if (i < EE * HH1) {                    // i = e*80+n
        g_W1sum[i] = W1[i] + W1[2 * EE * HH1 + i];
        float2 p;
        p.x = W1[EE * HH1 + i] - W1[2 * EE * HH1 + i];
        p.y = W1[3 * EE * HH1 + i];
        g_W1pair[i] = p;
    }
    if (i < HH2 * W2TSTRIDE) {
        int n = i / W2TSTRIDE, k = i - n * W2TSTRIDE;
        float v = (k < HH1) ? W2[k * HH2 + n] : 0.0f;
        g_W2T[i] = cvt_tf32(v);
    }
}

__global__ void prep_qw(const float* __restrict__ query, const float* __restrict__ b1) {
    __shared__ float sq[EE];
    int b = blockIdx.x, tid = threadIdx.x;
    if (tid < EE) sq[tid] = query[b * EE + tid];
    __syncthreads();
    if (tid < HH1) {
        float acc = b1[tid];
        #pragma unroll 8
        for (int e = 0; e < EE; e++)
            acc += sq[e] * g_W1sum[e * HH1 + tid];
        g_qW[b * HH1 + tid] = acc;
    }
}

// ---------------- smem layout (float index) ----------------
#define SM_B1   0                         // 80 x 68 = 5440 (tf32 bits, [n][e])
#define SM_W2T  5440                      // 40 x 84 = 3360 (tf32 bits)
#define SM_H1   8800                      // 4 warps x 16 x 84 = 5376 (tf32 bits)
#define SM_QW   14176                     // 80
#define SM_Q    14256                     // 64
#define SM_B2V  14320                     // 40
#define SM_WD   14360                     // 40
#define SM_SSC  14400                     // 208
#define SM_PART 14608                     // 128
#define SM_FLOATS 14736
#define SM_BYTES (SM_FLOATS * 4)          // 58944 -> 3 CTAs/SM

__global__ void __launch_bounds__(128, 3)
din_mma_kernel(const float* __restrict__ query,
               const float* __restrict__ keys,
               const void*  __restrict__ klen,
               const float* __restrict__ b2,
               const float* __restrict__ Wd,
               const float* __restrict__ bd,
               float* __restrict__ out)
{
    extern __shared__ float smf[];
    unsigned* smu = (unsigned*)smf;
    const int b    = blockIdx.x;
    const int tid  = threadIdx.x;
    const int wid  = tid >> 5;
    const int lane = tid & 31;
    const int gr   = lane >> 2;     // group row 0..7
    const int tg   = lane & 3;      // thread-in-group 0..3

    // ---- length (int64 vs silently-int32 jax) ----
    const long long* L64 = (const long long*)klen;
    const int*       L32 = (const int*)klen;
    bool is64 = ((ull)L64[0] <= 0xFFFFFFFFull) && ((ull)L64[1] <= 0xFFFFFFFFull) &&
                ((ull)L64[2] <= 0xFFFFFFFFull) && ((ull)L64[3] <= 0xFFFFFFFFull);
    int L = is64 ? (int)L64[b] : L32[b];
    if (L < 0) L = 0;
    if (L > TT) L = TT;
    if (L == 0) {
        if (tid < EE) out[b * EE + tid] = 0.0f;
        return;
    }
    const int ntiles = (L + 15) >> 4;
    const float* kb = keys + (size_t)b * TT * EE;

    // ---- stage scalars / W2T ----
    if (tid < EE)  smf[SM_Q + tid]  = query[b * EE + tid];
    if (tid < HH1) smf[SM_QW + tid] = g_qW[b * HH1 + tid];
    if (tid < HH2) { smf[SM_B2V + tid] = b2[tid]; smf[SM_WD + tid] = Wd[tid]; }
    {
        const uint4* src = (const uint4*)g_W2T;
        uint4* dst = (uint4*)&smu[SM_W2T];
        for (int i = tid; i < HH2 * W2TSTRIDE / 4; i += 128) dst[i] = src[i];
    }
    __syncthreads();

    // ---- B1eff: [n][e], tf32 bits:  bc + q_e * d ----
    for (int i = tid; i < EE * HH1; i += 128) {
        int n = i % HH1, e = i / HH1;
        float2 p = g_W1pair[e * HH1 + n];
        smu[SM_B1 + n * B1STRIDE + e] = cvt_tf32(p.x + smf[SM_Q + e] * p.y);
    }
    __syncthreads();

    const float bdv = bd[0];
    unsigned* h1 = &smu[SM_H1 + wid * 16 * H1STRIDE];

    // ---- warp-owned 16-token tiles ----
    for (int mt = wid; mt < ntiles; mt += 4) {
        const int rbase = mt * 16;
        const int r0 = rbase + gr, r1 = r0 + 8;
        const bool v0 = r0 < TT, v1 = r1 < TT;
        const float* k0 = kb + (size_t)r0 * EE + tg;
        const float* k1 = kb + (size_t)r1 * EE + tg;

        // fetch this thread's 32 k values straight from global
        float av0[16], av1[16];
        #pragma unroll
        for (int ks = 0; ks < 8; ks++) {
            av0[2 * ks]     = v0 ? k0[ks * 8]     : 0.0f;
            av0[2 * ks + 1] = v0 ? k0[ks * 8 + 4] : 0.0f;
            av1[2 * ks]     = v1 ? k1[ks * 8]     : 0.0f;
            av1[2 * ks + 1] = v1 ? k1[ks * 8 + 4] : 0.0f;
        }

        // MMA1: D1[16,80] = k @ B1eff
        float d1[10][4];
        #pragma unroll
        for (int nf = 0; nf < 10; nf++)
            d1[nf][0] = d1[nf][1] = d1[nf][2] = d1[nf][3] = 0.0f;

        #pragma unroll
        for (int ks = 0; ks < 8; ks++) {
            unsigned a0 = cvt_tf32(av0[2 * ks]);
            unsigned a1 = cvt_tf32(av1[2 * ks]);
            unsigned a2 = cvt_tf32(av0[2 * ks + 1]);
            unsigned a3 = cvt_tf32(av1[2 * ks + 1]);
            const unsigned* bb = &smu[SM_B1 + gr * B1STRIDE + ks * 8 + tg];
            #pragma unroll
            for (int nf = 0; nf < 10; nf++) {
                unsigned b0 = bb[nf * 8 * B1STRIDE];
                unsigned b1v = bb[nf * 8 * B1STRIDE + 4];
                mma_tf32(d1[nf], a0, a1, a2, a3, b0, b1v);
            }
        }

        // h1 = sigmoid(D1 + qW) -> smem (tf32 bits)
        #pragma unroll
        for (int nf = 0; nf < 10; nf++) {
            int j0 = nf * 8 + 2 * tg;
            float qlo = smf[SM_QW + j0], qhi = smf[SM_QW + j0 + 1];
            unsigned s0 = cvt_tf32(sigmoidf_fast(d1[nf][0] + qlo));
            unsigned s1 = cvt_tf32(sigmoidf_fast(d1[nf][1] + qhi));
            unsigned s2 = cvt_tf32(sigmoidf_fast(d1[nf][2] + qlo));
            unsigned s3 = cvt_tf32(sigmoidf_fast(d1[nf][3] + qhi));
            *(uint2*)&h1[gr * H1STRIDE + j0]       = make_uint2(s0, s1);
            *(uint2*)&h1[(gr + 8) * H1STRIDE + j0] = make_uint2(s2, s3);
        }
        __syncwarp();

        // MMA2: D2[16,40] = h1 @ W2T
        float d2[5][4];
        #pragma unroll
        for (int nf = 0; nf < 5; nf++)
            d2[nf][0] = d2[nf][1] = d2[nf][2] = d2[nf][3] = 0.0f;

        #pragma unroll
        for (int ks = 0; ks < 10; ks++) {
            const unsigned* ha = &h1[ks * 8 + tg];
            unsigned a0 = ha[gr * H1STRIDE];
            unsigned a1 = ha[(gr + 8) * H1STRIDE];
            unsigned a2 = ha[gr * H1STRIDE + 4];
            unsigned a3 = ha[(gr + 8) * H1STRIDE + 4];
            const unsigned* bb = &smu[SM_W2T + gr * W2TSTRIDE + ks * 8 + tg];
            #pragma unroll
            for (int nf = 0; nf < 5; nf++) {
                unsigned b0 = bb[nf * 8 * W2TSTRIDE];
                unsigned b1v = bb[nf * 8 * W2TSTRIDE + 4];
                mma_tf32(d2[nf], a0, a1, a2, a3, b0, b1v);
            }
        }

        // score = bd + sum_j sigmoid(D2+b2)*Wd ; reduce over tg
        float slo = 0.0f, shi = 0.0f;
        #pragma unroll
        for (int nf = 0; nf < 5; nf++) {
            int j0 = nf * 8 + 2 * tg;
            float blo = smf[SM_B2V + j0], bhi = smf[SM_B2V + j0 + 1];
            float wlo = smf[SM_WD + j0],  whi = smf[SM_WD + j0 + 1];
            slo += sigmoidf_fast(d2[nf][0] + blo) * wlo
                 + sigmoidf_fast(d2[nf][1] + bhi) * whi;
            shi += sigmoidf_fast(d2[nf][2] + blo) * wlo
                 + sigmoidf_fast(d2[nf][3] + bhi) * whi;
        }
        slo += __shfl_xor_sync(0xffffffffu, slo, 1);
        slo += __shfl_xor_sync(0xffffffffu, slo, 2);
        shi += __shfl_xor_sync(0xffffffffu, shi, 1);
        shi += __shfl_xor_sync(0xffffffffu, shi, 2);
        if (tg == 0) {
            int t0 = rbase + gr, t1 = rbase + gr + 8;
            if (t0 < L) smf[SM_SSC + t0] = slo + bdv;
            if (t1 < L) smf[SM_SSC + t1] = shi + bdv;
        }
    }
    __syncthreads();

    // ---- pooling: out[e] = sum_{t<L} score_t * k[t][e] (global k, coalesced) ----
    {
        int e = tid & 63, half = tid >> 6;
        const float* kp = kb + e;
        float acc = 0.0f;
        #pragma unroll 8
        for (int t = half; t < L; t += 2)
            acc += smf[SM_SSC + t] * kp[(size_t)t * EE];
        smf[SM_PART + tid] = acc;
    }
    __syncthreads();
    if (tid < EE)
        out[b * EE + tid] = smf[SM_PART + tid] + smf[SM_PART + EE + tid];
}

extern "C" void kernel_launch(void* const* d_in, const int* in_sizes, int n_in,
                              void* d_out, int out_size)
{
    const float* query = (const float*)d_in[0];
    const float* keys  = (const float*)d_in[1];
    const void*  klen  = d_in[2];
    const float* W1    = (const float*)d_in[3];
    const float* b1    = (const float*)d_in[4];
    const float* W2    = (const float*)d_in[5];
    const float* b2    = (const float*)d_in[6];
    const float* Wd    = (const float*)d_in[7];
    const float* bd    = (const float*)d_in[8];
    float* out = (float*)d_out;

    const int B = in_sizes[0] / EE;  // 4096

    static int configured = 0;
    if (!configured) {
        cudaFuncSetAttribute(din_mma_kernel,
                             cudaFuncAttributeMaxDynamicSharedMemorySize, SM_BYTES);
        configured = 1;
    }

    prep_pack<<<20, 256>>>(W1, W2);
    prep_qw<<<B, 128>>>(query, b1);
    din_mma_kernel<<<B, 128, SM_BYTES>>>(query, keys, klen, b2, Wd, bd, out);
}

// round 7
// speedup vs baseline: 2.3006x; 2.3006x over previous
#include <cuda_runtime.h>
#include <cstdint>

// DIN attention-seq-pooling, round 7: fp16 mma.sync m16n8k16 (f32 accum).
// vs round 5 (189.5us best): fp16 halves smem/LDS/MMA count; D1->A2 fragment
// alignment removes the h1 smem round-trip entirely; sigmoid via tanh.approx.
// smem 49.6KB -> 4 CTAs/SM. CTA = one batch, 4 warps, warp owns 16-token tiles.
//  MMA1: D1[16,80] = k[16,64] @ B1eff[64,80]   (fp16 in, fp32 acc)
//  h1 = sigmoid(D1 + qW) packed to half2 in regs (== MMA2 A-fragments)
//  MMA2: D2[16,40] = h1[16,80] @ W2T[80,40]
//  score = sigmoid(D2+b2)@Wd + bd, mask t<L; pool from GLOBAL fp32 k.

#define TT 200
#define EE 64
#define HH1 80
#define HH2 40
#define KSTR 36      // K row stride, uint(half2) units: ≡4 mod 32
#define B1STR 36     // B1eff row stride: ≡4 mod 32
#define W2STR 44     // W2T row stride: ≡12 mod 32 (12*gr+tg distinct mod 32)

typedef unsigned long long ull;

__device__ float  g_W1sum[EE * HH1];       // W1a + W1c, [e*80+n]
__device__ float2 g_W1pair[HH1 * EE];      // {W1b-W1c, W1d}, [n*64+e]
__device__ float  g_qW[4096 * HH1];        // b1 + q @ W1sum
__device__ unsigned g_W2Th[HH2 * W2STR];   // half2 image [n][k2], k<80 else 0

__device__ __forceinline__ unsigned pack_h2(float lo, float hi) {
    unsigned r;
    asm("cvt.rn.f16x2.f32 %0, %1, %2;" : "=r"(r) : "f"(hi), "f"(lo));
    return r;
}
__device__ __forceinline__ float sigmoid_tanh(float x) {
    float t;
    asm("tanh.approx.f32 %0, %1;" : "=f"(t) : "f"(x * 0.5f));
    return fmaf(t, 0.5f, 0.5f);
}
__device__ __forceinline__ void mma_f16(float* d, unsigned a0, unsigned a1,
                                        unsigned a2, unsigned a3,
                                        unsigned b0, unsigned b1) {
    asm volatile(
        "mma.sync.aligned.m16n8k16.row.col.f32.f16.f16.f32 "
        "{%0,%1,%2,%3}, {%4,%5,%6,%7}, {%8,%9}, {%0,%1,%2,%3};"
        : "+f"(d[0]), "+f"(d[1]), "+f"(d[2]), "+f"(d[3])
        : "r"(a0), "r"(a1), "r"(a2), "r"(a3), "r"(b0), "r"(b1));
}

// ---------------- prep kernels ----------------
__global__ void prep_pack(const float* __restrict__ W1, const float* __restrict__ W2) {
    int i = blockIdx.x * 256 + threadIdx.x;
    if (i < EE * HH1) {                    // i = e*80+n, coalesced W1 reads
        int e = i / HH1, n = i - e * HH1;
        g_W1sum[i] = W1[i] + W1[2 * EE * HH1 + i];
        float2 p;
        p.x = W1[EE * HH1 + i] - W1[2 * EE * HH1 + i];
        p.y = W1[3 * EE * HH1 + i];
        g_W1pair[n * EE + e] = p;
    }
    if (i < HH2 * W2STR) {
        int n = i / W2STR, k2 = i - n * W2STR;
        float v0 = (2 * k2 < HH1)     ? W2[(2 * k2) * HH2 + n]     : 0.0f;
        float v1 = (2 * k2 + 1 < HH1) ? W2[(2 * k2 + 1) * HH2 + n] : 0.0f;
        g_W2Th[i] = pack_h2(v0, v1);
    }
}

__global__ void prep_qw(const float* __restrict__ query, const float* __restrict__ b1) {
    __shared__ float sq[EE];
    int b = blockIdx.x, tid = threadIdx.x;
    if (tid < EE) sq[tid] = query[b * EE + tid];
    __syncthreads();
    if (tid < HH1) {
        float acc = b1[tid];
        #pragma unroll 8
        for (int e = 0; e < EE; e++)
            acc += sq[e] * g_W1sum[e * HH1 + tid];
        g_qW[b * HH1 + tid] = acc;
    }
}

// ---------------- smem layout (32-bit word index) ----------------
#define SM_K    0                         // 208 x 36 half2 = 7488
#define SM_B1   7488                      // 80 x 36 = 2880
#define SM_W2T  10368                     // 40 x 44 = 1760
#define SM_QW   12128                     // 80 f
#define SM_Q    12208                     // 64 f
#define SM_B2V  12272                     // 40 f
#define SM_WD   12312                     // 40 f
#define SM_SSC  12352                     // 208 f
#define SM_PART 12560                     // 128 f
#define SM_WORDS 12688
#define SM_BYTES (SM_WORDS * 4)           // 50752 -> 4 CTAs/SM

__global__ void __launch_bounds__(128, 4)
din_mma_kernel(const float* __restrict__ query,
               const float* __restrict__ keys,
               const void*  __restrict__ klen,
               const float* __restrict__ b2,
               const float* __restrict__ Wd,
               const float* __restrict__ bd,
               float* __restrict__ out)
{
    extern __shared__ float smf[];
    unsigned* smu = (unsigned*)smf;
    const int b    = blockIdx.x;
    const int tid  = threadIdx.x;
    const int wid  = tid >> 5;
    const int lane = tid & 31;
    const int gr   = lane >> 2;     // group row 0..7
    const int tg   = lane & 3;      // thread-in-group 0..3

    // ---- length (int64 vs silently-int32 jax) ----
    const long long* L64 = (const long long*)klen;
    const int*       L32 = (const int*)klen;
    bool is64 = ((ull)L64[0] <= 0xFFFFFFFFull) && ((ull)L64[1] <= 0xFFFFFFFFull) &&
                ((ull)L64[2] <= 0xFFFFFFFFull) && ((ull)L64[3] <= 0xFFFFFFFFull);
    int L = is64 ? (int)L64[b] : L32[b];
    if (L < 0) L = 0;
    if (L > TT) L = TT;
    if (L == 0) {
        if (tid < EE) out[b * EE + tid] = 0.0f;
        return;
    }
    const int ntiles = (L + 15) >> 4;
    const float* kb = keys + (size_t)b * TT * EE;

    // ---- stage scalars / W2T ----
    if (tid < EE)  smf[SM_Q + tid]  = query[b * EE + tid];
    if (tid < HH1) smf[SM_QW + tid] = g_qW[b * HH1 + tid];
    if (tid < HH2) { smf[SM_B2V + tid] = b2[tid]; smf[SM_WD + tid] = Wd[tid]; }
    {
        const uint2* src = (const uint2*)g_W2Th;
        uint2* dst = (uint2*)&smu[SM_W2T];
        for (int i = tid; i < HH2 * W2STR / 2; i += 128) dst[i] = src[i];
    }

    // ---- stage k rows [0, ntiles*16) as half2, coalesced ----
    {
        const int nrows = ntiles * 16;
        for (int i = tid; i < nrows * 16; i += 128) {
            int r = i >> 4, c4 = i & 15;            // c4 = float4 index
            float4 v = make_float4(0.f, 0.f, 0.f, 0.f);
            if (r < TT) v = *(const float4*)(kb + (size_t)r * EE + c4 * 4);
            uint2 h;
            h.x = pack_h2(v.x, v.y);
            h.y = pack_h2(v.z, v.w);
            *(uint2*)&smu[SM_K + r * KSTR + c4 * 2] = h;
        }
    }
    __syncthreads();

    // ---- B1eff half2 image: [n][e2],  bc + q_e * d ----
    for (int i = tid; i < HH1 * (EE / 2); i += 128) {
        int n = i >> 5, e2 = i & 31;
        float4 w = *(const float4*)&g_W1pair[n * EE + 2 * e2];   // {bc0,d0,bc1,d1}
        float q0 = smf[SM_Q + 2 * e2], q1 = smf[SM_Q + 2 * e2 + 1];
        smu[SM_B1 + n * B1STR + e2] = pack_h2(fmaf(q0, w.y, w.x),
                                              fmaf(q1, w.w, w.z));
    }
    __syncthreads();

    const float bdv = bd[0];

    // ---- warp-owned 16-token tiles ----
    for (int mt = wid; mt < ntiles; mt += 4) {
        const int rbase = mt * 16;
        const int r0 = rbase + gr, r1 = r0 + 8;
        const unsigned* kr0 = &smu[SM_K + r0 * KSTR + tg];
        const unsigned* kr1 = &smu[SM_K + r1 * KSTR + tg];

        // MMA1: D1[16,80] = k @ B1eff  (4 ksteps of 16)
        float d1[10][4];
        #pragma unroll
        for (int nf = 0; nf < 10; nf++)
            d1[nf][0] = d1[nf][1] = d1[nf][2] = d1[nf][3] = 0.0f;

        #pragma unroll
        for (int ks = 0; ks < 4; ks++) {
            unsigned a0 = kr0[8 * ks];
            unsigned a1 = kr1[8 * ks];
            unsigned a2 = kr0[8 * ks + 4];
            unsigned a3 = kr1[8 * ks + 4];
            const unsigned* bb = &smu[SM_B1 + gr * B1STR + 8 * ks + tg];
            #pragma unroll
            for (int nf = 0; nf < 10; nf++) {
                unsigned b0 = bb[nf * 8 * B1STR];
                unsigned b1v = bb[nf * 8 * B1STR + 4];
                mma_f16(d1[nf], a0, a1, a2, a3, b0, b1v);
            }
        }

        // h1 = sigmoid(D1 + qW) packed half2 in regs == MMA2 A-fragments.
        // haA[nf] = rows gr  (cols 8nf+2tg, +1); haB[nf] = rows gr+8.
        unsigned haA[10], haB[10];
        #pragma unroll
        for (int nf = 0; nf < 10; nf++) {
            int j0 = nf * 8 + 2 * tg;
            float qlo = smf[SM_QW + j0], qhi = smf[SM_QW + j0 + 1];
            haA[nf] = pack_h2(sigmoid_tanh(d1[nf][0] + qlo),
                              sigmoid_tanh(d1[nf][1] + qhi));
            haB[nf] = pack_h2(sigmoid_tanh(d1[nf][2] + qlo),
                              sigmoid_tanh(d1[nf][3] + qhi));
        }

        // MMA2: D2[16,40] = h1 @ W2T  (5 ksteps of 16)
        float d2[5][4];
        #pragma unroll
        for (int nf = 0; nf < 5; nf++)
            d2[nf][0] = d2[nf][1] = d2[nf][2] = d2[nf][3] = 0.0f;

        #pragma unroll
        for (int ks = 0; ks < 5; ks++) {
            unsigned a0 = haA[2 * ks];
            unsigned a1 = haB[2 * ks];
            unsigned a2 = haA[2 * ks + 1];
            unsigned a3 = haB[2 * ks + 1];
            const unsigned* bb = &smu[SM_W2T + gr * W2STR + 8 * ks + tg];
            #pragma unroll
            for (int nf = 0; nf < 5; nf++) {
                unsigned b0 = bb[nf * 8 * W2STR];
                unsigned b1v = bb[nf * 8 * W2STR + 4];
                mma_f16(d2[nf], a0, a1, a2, a3, b0, b1v);
            }
        }

        // score = bd + sum_j sigmoid(D2+b2)*Wd ; reduce over tg
        float slo = 0.0f, shi = 0.0f;
        #pragma unroll
        for (int nf = 0; nf < 5; nf++) {
            int j0 = nf * 8 + 2 * tg;
            float blo = smf[SM_B2V + j0], bhi = smf[SM_B2V + j0 + 1];
            float wlo = smf[SM_WD + j0],  whi = smf[SM_WD + j0 + 1];
            slo += sigmoid_tanh(d2[nf][0] + blo) * wlo
                 + sigmoid_tanh(d2[nf][1] + bhi) * whi;
            shi += sigmoid_tanh(d2[nf][2] + blo) * wlo
                 + sigmoid_tanh(d2[nf][3] + bhi) * whi;
        }
        slo += __shfl_xor_sync(0xffffffffu, slo, 1);
        slo += __shfl_xor_sync(0xffffffffu, slo, 2);
        shi += __shfl_xor_sync(0xffffffffu, shi, 1);
        shi += __shfl_xor_sync(0xffffffffu, shi, 2);
        if (tg == 0) {
            int t0 = rbase + gr, t1 = rbase + gr + 8;
            if (t0 < L) smf[SM_SSC + t0] = slo + bdv;
            if (t1 < L) smf[SM_SSC + t1] = shi + bdv;
        }
    }
    __syncthreads();

    // ---- pooling from GLOBAL fp32 k (coalesced 256B per t) ----
    {
        int e = tid & 63, half = tid >> 6;
        const float* kp = kb + e;
        float acc = 0.0f;
        #pragma unroll 8
        for (int t = half; t < L; t += 2)
            acc += smf[SM_SSC + t] * kp[(size_t)t * EE];
        smf[SM_PART + tid] = acc;
    }
    __syncthreads();
    if (tid < EE)
        out[b * EE + tid] = smf[SM_PART + tid] + smf[SM_PART + EE + tid];
}

extern "C" void kernel_launch(void* const* d_in, const int* in_sizes, int n_in,
                              void* d_out, int out_size)
{
    const float* query = (const float*)d_in[0];
    const float* keys  = (const float*)d_in[1];
    const void*  klen  = d_in[2];
    const float* W1    = (const float*)d_in[3];
    const float* b1    = (const float*)d_in[4];
    const float* W2    = (const float*)d_in[5];
    const float* b2    = (const float*)d_in[6];
    const float* Wd    = (const float*)d_in[7];
    const float* bd    = (const float*)d_in[8];
    float* out = (float*)d_out;

    const int B = in_sizes[0] / EE;  // 4096

    static int configured = 0;
    if (!configured) {
        cudaFuncSetAttribute(din_mma_kernel,
                             cudaFuncAttributeMaxDynamicSharedMemorySize, SM_BYTES);
        configured = 1;
    }

    prep_pack<<<20, 256>>>(W1, W2);
    prep_qw<<<B, 128>>>(query, b1);
    din_mma_kernel<<<B, 128, SM_BYTES>>>(query, keys, klen, b2, Wd, bd, out);
}